// round 2
// baseline (speedup 1.0000x reference)
#include <cuda_runtime.h>
#include <math.h>

// Compacted-buffer formulation:
//   layer i: out[c, j] = tanh( sum_k W[i,c,k,0]*in[k,2j] + W[i,c,k,1]*in[k,2j+1] + b[i,c] )
//   => GEMM: A = W[i] viewed as (256 x 512) row-major (exactly its storage layout),
//            B[2k+t, j] = in[k, 2j+t],  C = (256 x Nout)
// N halves each layer: 65536 -> 32768 -> ... -> 1.

#define BM 128
#define BN 128
#define BK 16
#define TM 8
#define TN 8

// ping-pong scratch (even layers write buf0, odd layers write buf1)
__device__ float g_buf0[256 * 32768];   // 32 MB
__device__ float g_buf1[256 * 16384];   // 16 MB

__global__ __launch_bounds__(256) void layer_kernel(
    const float* __restrict__ in,    // 256 x Nin, row-major
    const float* __restrict__ W,     // 256 x 512, row-major (one layer)
    const float* __restrict__ bias,  // 256
    float* __restrict__ out,         // 256 x Nout, row-major
    int Nin, int Nout)
{
    __shared__ float sA[BK][BM + 1];   // transposed A tile: sA[kk][m], pad to dodge bank conflicts
    __shared__ float sB[BK][BN];       // sB[kk][j]

    const int tid = threadIdx.x;          // 0..255
    const int tx  = tid & 15;             // col group
    const int ty  = tid >> 4;             // row group
    const int m0  = blockIdx.y * BM;
    const int j0  = blockIdx.x * BN;

    float acc[TM][TN];
    #pragma unroll
    for (int i = 0; i < TM; i++)
        #pragma unroll
        for (int j = 0; j < TN; j++) acc[i][j] = 0.f;

    for (int k0 = 0; k0 < 512; k0 += BK) {
        // ---- load A tile (128 x 16) transposed into smem ----
        // 2048 floats = 512 float4 loads; 2 per thread
        #pragma unroll
        for (int it = 0; it < 2; it++) {
            int idx = tid + it * 256;        // 0..511
            int row = idx >> 2;              // 0..127
            int kq  = idx & 3;               // 0..3
            float4 v = *reinterpret_cast<const float4*>(
                &W[(m0 + row) * 512 + k0 + kq * 4]);
            sA[kq * 4 + 0][row] = v.x;
            sA[kq * 4 + 1][row] = v.y;
            sA[kq * 4 + 2][row] = v.z;
            sA[kq * 4 + 3][row] = v.w;
        }
        // ---- load B tile (16 x 128) ----
        // B[kk][j] = in[(k0+kk)>>1][2*(j0+j) + (kk&1)]
        // = 8 channels x 256 consecutive time samples (coalesced global reads)
        #pragma unroll
        for (int it = 0; it < 8; it++) {
            int idx = tid + it * 256;        // 0..2047
            int cc  = idx >> 8;              // 0..7 (channel within tile)
            int mm  = idx & 255;             // 0..255 (time offset)
            int ch  = (k0 >> 1) + cc;
            int t   = 2 * j0 + mm;
            float v = (t < Nin) ? in[ch * Nin + t] : 0.f;
            sB[2 * cc + (mm & 1)][mm >> 1] = v;
        }
        __syncthreads();

        // ---- compute ----
        #pragma unroll
        for (int kk = 0; kk < BK; kk++) {
            float a[TM];
            float bb[TN];
            #pragma unroll
            for (int i = 0; i < TM; i++) a[i] = sA[kk][ty * TM + i];
            float4 b0 = *reinterpret_cast<const float4*>(&sB[kk][tx * TN]);
            float4 b1 = *reinterpret_cast<const float4*>(&sB[kk][tx * TN + 4]);
            bb[0] = b0.x; bb[1] = b0.y; bb[2] = b0.z; bb[3] = b0.w;
            bb[4] = b1.x; bb[5] = b1.y; bb[6] = b1.z; bb[7] = b1.w;
            #pragma unroll
            for (int i = 0; i < TM; i++)
                #pragma unroll
                for (int j = 0; j < TN; j++)
                    acc[i][j] += a[i] * bb[j];
        }
        __syncthreads();
    }

    // ---- epilogue: bias + tanh + store ----
    #pragma unroll
    for (int i = 0; i < TM; i++) {
        int m = m0 + ty * TM + i;
        float bv = bias[m];
        #pragma unroll
        for (int j = 0; j < TN; j++) {
            int col = j0 + tx * TN + j;
            if (col < Nout)
                out[m * Nout + col] = tanhf(acc[i][j] + bv);
        }
    }
}

extern "C" void kernel_launch(void* const* d_in, const int* in_sizes, int n_in,
                              void* d_out, int out_size)
{
    const float* x = (const float*)d_in[0];   // (1, 256, 65536)
    const float* W = (const float*)d_in[1];   // (16, 256, 256, 2)
    const float* b = (const float*)d_in[2];   // (16, 256)

    float* buf0 = nullptr;
    float* buf1 = nullptr;
    cudaGetSymbolAddress((void**)&buf0, g_buf0);
    cudaGetSymbolAddress((void**)&buf1, g_buf1);

    int Nin = 65536;
    const float* cur = x;
    for (int i = 0; i < 16; i++) {
        int Nout = Nin >> 1;
        float* outp = (i == 15) ? (float*)d_out : ((i & 1) ? buf1 : buf0);
        dim3 grid((Nout + BN - 1) / BN, 2);
        layer_kernel<<<grid, 256>>>(cur, W + (size_t)i * 256 * 512,
                                    b + i * 256, outp, Nin, Nout);
        cur = outp;
        Nin = Nout;
    }
}

// round 3
// speedup vs baseline: 1.0475x; 1.0475x over previous
#include <cuda_runtime.h>
#include <math.h>

// Compacted-buffer formulation:
//   layer i: out[c, j] = tanh( sum_k W[i,c,k,0]*in[k,2j] + W[i,c,k,1]*in[k,2j+1] + b[i,c] )
//   => GEMM: A = W[i] viewed as (256 x 512) row-major (exactly its storage layout),
//            B[2k+t, j] = in[k, 2j+t],  C = (256 x Nout)
// N halves each layer: 65536 -> 32768 -> ... -> 1.

#define BM 128
#define BN 128
#define BK 16
#define TM 8
#define TN 8

// ping-pong scratch (even layers write buf0, odd layers write buf1)
__device__ float g_buf0[256 * 32768];   // 32 MB
__device__ float g_buf1[256 * 16384];   // 16 MB

__global__ __launch_bounds__(256) void layer_kernel(
    const float* __restrict__ in,    // 256 x Nin, row-major
    const float* __restrict__ W,     // 256 x 512, row-major (one layer)
    const float* __restrict__ bias,  // 256
    float* __restrict__ out,         // 256 x Nout, row-major
    int Nin, int Nout)
{
    __shared__ float sA[BK][BM + 1];   // transposed A tile: sA[kk][m], pad to dodge bank conflicts
    __shared__ float sB[BK][BN];       // sB[kk][j]

    const int tid = threadIdx.x;          // 0..255
    const int tx  = tid & 15;             // col group
    const int ty  = tid >> 4;             // row group
    const int m0  = blockIdx.y * BM;
    const int j0  = blockIdx.x * BN;

    float acc[TM][TN];
    #pragma unroll
    for (int i = 0; i < TM; i++)
        #pragma unroll
        for (int j = 0; j < TN; j++) acc[i][j] = 0.f;

    for (int k0 = 0; k0 < 512; k0 += BK) {
        // ---- load A tile (128 x 16) transposed into smem ----
        // 2048 floats = 512 float4 loads; 2 per thread
        #pragma unroll
        for (int it = 0; it < 2; it++) {
            int idx = tid + it * 256;        // 0..511
            int row = idx >> 2;              // 0..127
            int kq  = idx & 3;               // 0..3
            float4 v = *reinterpret_cast<const float4*>(
                &W[(m0 + row) * 512 + k0 + kq * 4]);
            sA[kq * 4 + 0][row] = v.x;
            sA[kq * 4 + 1][row] = v.y;
            sA[kq * 4 + 2][row] = v.z;
            sA[kq * 4 + 3][row] = v.w;
        }
        // ---- load B tile (16 x 128) ----
        // B[kk][j] = in[(k0+kk)>>1][2*(j0+j) + (kk&1)]
        // = 8 channels x 256 consecutive time samples (coalesced global reads)
        #pragma unroll
        for (int it = 0; it < 8; it++) {
            int idx = tid + it * 256;        // 0..2047
            int cc  = idx >> 8;              // 0..7 (channel within tile)
            int mm  = idx & 255;             // 0..255 (time offset)
            int ch  = (k0 >> 1) + cc;
            int t   = 2 * j0 + mm;
            float v = (t < Nin) ? in[ch * Nin + t] : 0.f;
            sB[2 * cc + (mm & 1)][mm >> 1] = v;
        }
        __syncthreads();

        // ---- compute ----
        #pragma unroll
        for (int kk = 0; kk < BK; kk++) {
            float a[TM];
            float bb[TN];
            #pragma unroll
            for (int i = 0; i < TM; i++) a[i] = sA[kk][ty * TM + i];
            float4 b0 = *reinterpret_cast<const float4*>(&sB[kk][tx * TN]);
            float4 b1 = *reinterpret_cast<const float4*>(&sB[kk][tx * TN + 4]);
            bb[0] = b0.x; bb[1] = b0.y; bb[2] = b0.z; bb[3] = b0.w;
            bb[4] = b1.x; bb[5] = b1.y; bb[6] = b1.z; bb[7] = b1.w;
            #pragma unroll
            for (int i = 0; i < TM; i++)
                #pragma unroll
                for (int j = 0; j < TN; j++)
                    acc[i][j] += a[i] * bb[j];
        }
        __syncthreads();
    }

    // ---- epilogue: bias + tanh + store ----
    #pragma unroll
    for (int i = 0; i < TM; i++) {
        int m = m0 + ty * TM + i;
        float bv = bias[m];
        #pragma unroll
        for (int j = 0; j < TN; j++) {
            int col = j0 + tx * TN + j;
            if (col < Nout)
                out[m * Nout + col] = tanhf(acc[i][j] + bv);
        }
    }
}

extern "C" void kernel_launch(void* const* d_in, const int* in_sizes, int n_in,
                              void* d_out, int out_size)
{
    const float* x = (const float*)d_in[0];   // (1, 256, 65536)
    const float* W = (const float*)d_in[1];   // (16, 256, 256, 2)
    const float* b = (const float*)d_in[2];   // (16, 256)

    float* buf0 = nullptr;
    float* buf1 = nullptr;
    cudaGetSymbolAddress((void**)&buf0, g_buf0);
    cudaGetSymbolAddress((void**)&buf1, g_buf1);

    int Nin = 65536;
    const float* cur = x;
    for (int i = 0; i < 16; i++) {
        int Nout = Nin >> 1;
        float* outp = (i == 15) ? (float*)d_out : ((i & 1) ? buf1 : buf0);
        dim3 grid((Nout + BN - 1) / BN, 2);
        layer_kernel<<<grid, 256>>>(cur, W + (size_t)i * 256 * 512,
                                    b + i * 256, outp, Nin, Nout);
        cur = outp;
        Nin = Nout;
    }
}

// round 5
// speedup vs baseline: 1.9069x; 1.8204x over previous
#include <cuda_runtime.h>
#include <cuda_bf16.h>
#include <cstdint>
#include <math.h>

// ============================================================
// bf16-split GEMM per layer via mma.sync (HMMA) — portable to
// plain sm_103 target (no tcgen05; toolchain emits .target sm_103).
//   layer i: out[c,j] = tanh( sum_k W[c,k]*B[k,j] + bias[c] )
//   B[k][j] = in[k>>1][2j + (k&1)]   (compacted dilated conv)
//   fp32 ~= bf16 hi+lo:  A*B ~= Ah*Bh + Ah*Bl + Al*Bh
// Activations carried between layers as bf16 hi/lo planes.
// ============================================================

#define RS 80   // smem row stride in bytes (64B payload + pad)

// ---------------- scratch ----------------
__device__ __nv_bfloat16 g_ahi[256 * 32768];
__device__ __nv_bfloat16 g_alo[256 * 32768];
__device__ __nv_bfloat16 g_bhi[256 * 16384];
__device__ __nv_bfloat16 g_blo[256 * 16384];
__device__ __nv_bfloat16 g_whi[16 * 256 * 512];
__device__ __nv_bfloat16 g_wlo[16 * 256 * 512];

// ---------------- helpers ----------------
__device__ __forceinline__ void ldsm_x4(uint32_t* r, uint32_t addr) {
    asm volatile("ldmatrix.sync.aligned.m8n8.x4.shared.b16 {%0,%1,%2,%3}, [%4];"
        : "=r"(r[0]), "=r"(r[1]), "=r"(r[2]), "=r"(r[3]) : "r"(addr));
}

__device__ __forceinline__ void mma_bf16(float* c, const uint32_t* a, const uint32_t* b) {
    asm volatile(
        "mma.sync.aligned.m16n8k16.row.col.f32.bf16.bf16.f32 "
        "{%0,%1,%2,%3}, {%4,%5,%6,%7}, {%8,%9}, {%0,%1,%2,%3};"
        : "+f"(c[0]), "+f"(c[1]), "+f"(c[2]), "+f"(c[3])
        : "r"(a[0]), "r"(a[1]), "r"(a[2]), "r"(a[3]), "r"(b[0]), "r"(b[1]));
}

// split two floats into packed-bf16 hi pair and lo (residual) pair
__device__ __forceinline__ void split2(float x, float y, uint32_t& h, uint32_t& l) {
    __nv_bfloat16 hx = __float2bfloat16(x);
    __nv_bfloat16 hy = __float2bfloat16(y);
    __nv_bfloat162 hp; hp.x = hx; hp.y = hy;
    __nv_bfloat162 lp;
    lp.x = __float2bfloat16(x - __bfloat162float(hx));
    lp.y = __float2bfloat16(y - __bfloat162float(hy));
    h = *reinterpret_cast<uint32_t*>(&hp);
    l = *reinterpret_cast<uint32_t*>(&lp);
}

// ---------------- weight hi/lo split ----------------
__global__ void prep_w(const float* __restrict__ W,
                       __nv_bfloat16* __restrict__ hi,
                       __nv_bfloat16* __restrict__ lo, int n) {
    int i = blockIdx.x * blockDim.x + threadIdx.x;
    if (i < n) {
        float v = W[i];
        __nv_bfloat16 h = __float2bfloat16(v);
        hi[i] = h;
        lo[i] = __float2bfloat16(v - __bfloat162float(h));
    }
}

// ---------------- per-layer GEMM kernel ----------------
// CTA: 256 threads = 8 warps in 2(M) x 4(N) grid; tile 128x128, BK=32.
__global__ __launch_bounds__(256) void layer_hmma(
    const void* __restrict__ in_hi,          // bf16 plane, or fp32 if fp32_in
    const __nv_bfloat16* __restrict__ in_lo, // bf16 lo plane (ignored if fp32_in)
    const __nv_bfloat16* __restrict__ Whi,   // 256 x 512
    const __nv_bfloat16* __restrict__ Wlo,
    const float* __restrict__ bias,          // 256
    __nv_bfloat16* __restrict__ out_hi,      // 256 x Nout
    __nv_bfloat16* __restrict__ out_lo,
    float* __restrict__ out_f,               // non-null on final layer (Nout==1)
    int Nin, int Nout, int fp32_in)
{
    __shared__ __align__(16) char sAh[128 * RS];
    __shared__ __align__(16) char sAl[128 * RS];
    __shared__ __align__(16) char sBh[128 * RS];
    __shared__ __align__(16) char sBl[128 * RS];

    const int tid  = threadIdx.x;
    const int lane = tid & 31;
    const int wid  = tid >> 5;
    const int wm   = wid & 1;     // 0..1 : 64-row slab
    const int wn   = wid >> 1;    // 0..3 : 32-col slab
    const int m0   = blockIdx.y * 128;
    const int j0   = blockIdx.x * 128;

    float acc[4][4][4];
    #pragma unroll
    for (int a = 0; a < 4; a++)
        #pragma unroll
        for (int b = 0; b < 4; b++)
            #pragma unroll
            for (int c = 0; c < 4; c++) acc[a][b][c] = 0.f;

    const uint32_t sAh_u = (uint32_t)__cvta_generic_to_shared(sAh);
    const uint32_t sAl_u = (uint32_t)__cvta_generic_to_shared(sAl);
    const uint32_t sBh_u = (uint32_t)__cvta_generic_to_shared(sBh);
    const uint32_t sBl_u = (uint32_t)__cvta_generic_to_shared(sBl);

    // ldmatrix per-lane source rows
    const int a_row = lane & 15;
    const int a_cb  = lane >> 4;                      // k 16B-block (x4 tile pair)
    const int b_row = (lane & 7) + ((lane >> 4) << 3);
    const int b_cb  = (lane >> 3) & 1;

    // loader mapping
    const int l_arow = tid >> 1, l_ahalf = tid & 1;   // A: 128 rows x 2 halves
    const int l_c = tid & 15, l_seg = tid >> 4;       // B: 16 chans x 16 segments

    for (int chunk = 0; chunk < 16; chunk++) {
        const int k0 = chunk * 32;

        // ---- A tile: 128 x 32 bf16 (hi & lo), row-major K-contig ----
        {
            size_t gofs = (size_t)(m0 + l_arow) * 512 + k0 + l_ahalf * 16;
            const uint4* ph = reinterpret_cast<const uint4*>(Whi + gofs);
            const uint4* pl = reinterpret_cast<const uint4*>(Wlo + gofs);
            uint4 h0 = ph[0], h1 = ph[1];
            uint4 l0 = pl[0], l1 = pl[1];
            char* dh = sAh + l_arow * RS + l_ahalf * 32;
            char* dl = sAl + l_arow * RS + l_ahalf * 32;
            reinterpret_cast<uint4*>(dh)[0] = h0;
            reinterpret_cast<uint4*>(dh)[1] = h1;
            reinterpret_cast<uint4*>(dl)[0] = l0;
            reinterpret_cast<uint4*>(dl)[1] = l1;
        }

        // ---- B tile: sB[j][k] = in[(k0+k)>>1][2(j0+j) + (k&1)], [n][k] layout ----
        {
            const int ch = (k0 >> 1) + l_c;
            const int t  = 2 * j0 + l_seg * 16;       // 16 consecutive times
            uint32_t vh[8], vl[8];
            if (fp32_in) {
                const float* p = reinterpret_cast<const float*>(in_hi) + (size_t)ch * Nin + t;
                if (t + 15 < Nin) {
                    #pragma unroll
                    for (int q = 0; q < 4; q++) {
                        float4 f = reinterpret_cast<const float4*>(p)[q];
                        split2(f.x, f.y, vh[2 * q],     vl[2 * q]);
                        split2(f.z, f.w, vh[2 * q + 1], vl[2 * q + 1]);
                    }
                } else {
                    #pragma unroll
                    for (int q = 0; q < 8; q++) {
                        float f0 = (t + 2 * q     < Nin) ? p[2 * q]     : 0.f;
                        float f1 = (t + 2 * q + 1 < Nin) ? p[2 * q + 1] : 0.f;
                        split2(f0, f1, vh[q], vl[q]);
                    }
                }
            } else {
                const __nv_bfloat16* ph = reinterpret_cast<const __nv_bfloat16*>(in_hi) + (size_t)ch * Nin + t;
                const __nv_bfloat16* pl = in_lo + (size_t)ch * Nin + t;
                if (t + 15 < Nin) {
                    uint4 u0 = reinterpret_cast<const uint4*>(ph)[0];
                    uint4 u1 = reinterpret_cast<const uint4*>(ph)[1];
                    uint4 w0 = reinterpret_cast<const uint4*>(pl)[0];
                    uint4 w1 = reinterpret_cast<const uint4*>(pl)[1];
                    vh[0] = u0.x; vh[1] = u0.y; vh[2] = u0.z; vh[3] = u0.w;
                    vh[4] = u1.x; vh[5] = u1.y; vh[6] = u1.z; vh[7] = u1.w;
                    vl[0] = w0.x; vl[1] = w0.y; vl[2] = w0.z; vl[3] = w0.w;
                    vl[4] = w1.x; vl[5] = w1.y; vl[6] = w1.z; vl[7] = w1.w;
                } else {
                    #pragma unroll
                    for (int q = 0; q < 8; q++) {
                        __nv_bfloat162 hp, lp;
                        hp.x = (t + 2 * q     < Nin) ? ph[2 * q]     : __nv_bfloat16(0.f);
                        hp.y = (t + 2 * q + 1 < Nin) ? ph[2 * q + 1] : __nv_bfloat16(0.f);
                        lp.x = (t + 2 * q     < Nin) ? pl[2 * q]     : __nv_bfloat16(0.f);
                        lp.y = (t + 2 * q + 1 < Nin) ? pl[2 * q + 1] : __nv_bfloat16(0.f);
                        vh[q] = *reinterpret_cast<uint32_t*>(&hp);
                        vl[q] = *reinterpret_cast<uint32_t*>(&lp);
                    }
                }
            }
            char* dh = sBh + (l_seg * 8) * RS + 4 * l_c;
            char* dl = sBl + (l_seg * 8) * RS + 4 * l_c;
            #pragma unroll
            for (int q = 0; q < 8; q++) {
                *reinterpret_cast<uint32_t*>(dh + q * RS) = vh[q];
                *reinterpret_cast<uint32_t*>(dl + q * RS) = vl[q];
            }
        }
        __syncthreads();

        // ---- compute: 2 k16 steps x (AhBh + AhBl + AlBh) ----
        #pragma unroll
        for (int ks = 0; ks < 2; ks++) {
            uint32_t af[4][4], bh[4][2], bl[4][2];
            #pragma unroll
            for (int mt = 0; mt < 4; mt++) {
                uint32_t ofs = (uint32_t)((wm * 64 + mt * 16 + a_row) * RS + ks * 32 + a_cb * 16);
                ldsm_x4(af[mt], sAh_u + ofs);
            }
            #pragma unroll
            for (int half = 0; half < 2; half++) {
                uint32_t ofs = (uint32_t)((wn * 32 + half * 16 + b_row) * RS + ks * 32 + b_cb * 16);
                uint32_t r[4];
                ldsm_x4(r, sBh_u + ofs);
                bh[half * 2][0] = r[0]; bh[half * 2][1] = r[1];
                bh[half * 2 + 1][0] = r[2]; bh[half * 2 + 1][1] = r[3];
                ldsm_x4(r, sBl_u + ofs);
                bl[half * 2][0] = r[0]; bl[half * 2][1] = r[1];
                bl[half * 2 + 1][0] = r[2]; bl[half * 2 + 1][1] = r[3];
            }
            #pragma unroll
            for (int mt = 0; mt < 4; mt++)
                #pragma unroll
                for (int nt = 0; nt < 4; nt++) {
                    mma_bf16(acc[mt][nt], af[mt], bh[nt]);
                    mma_bf16(acc[mt][nt], af[mt], bl[nt]);
                }
            #pragma unroll
            for (int mt = 0; mt < 4; mt++) {
                uint32_t ofs = (uint32_t)((wm * 64 + mt * 16 + a_row) * RS + ks * 32 + a_cb * 16);
                ldsm_x4(af[mt], sAl_u + ofs);
            }
            #pragma unroll
            for (int mt = 0; mt < 4; mt++)
                #pragma unroll
                for (int nt = 0; nt < 4; nt++)
                    mma_bf16(acc[mt][nt], af[mt], bh[nt]);
        }
        __syncthreads();
    }

    // ---- epilogue: bias + tanh; write bf16 hi/lo planes (or fp32 final) ----
    const int g = lane >> 2, tig = lane & 3;
    #pragma unroll
    for (int mt = 0; mt < 4; mt++) {
        const int mA = m0 + wm * 64 + mt * 16 + g;
        const int mB = mA + 8;
        const float bA = bias[mA], bB = bias[mB];
        #pragma unroll
        for (int nt = 0; nt < 4; nt++) {
            const int col = j0 + wn * 32 + nt * 8 + 2 * tig;
            float v0 = tanhf(acc[mt][nt][0] + bA);
            float v1 = tanhf(acc[mt][nt][1] + bA);
            float v2 = tanhf(acc[mt][nt][2] + bB);
            float v3 = tanhf(acc[mt][nt][3] + bB);
            if (out_f) {
                if (col == 0) { out_f[mA] = v0; out_f[mB] = v2; }
            } else if (col < Nout) {   // Nout even for all intermediate layers
                uint32_t h, l;
                split2(v0, v1, h, l);
                *reinterpret_cast<uint32_t*>(out_hi + (size_t)mA * Nout + col) = h;
                *reinterpret_cast<uint32_t*>(out_lo + (size_t)mA * Nout + col) = l;
                split2(v2, v3, h, l);
                *reinterpret_cast<uint32_t*>(out_hi + (size_t)mB * Nout + col) = h;
                *reinterpret_cast<uint32_t*>(out_lo + (size_t)mB * Nout + col) = l;
            }
        }
    }
}

// ---------------- host ----------------
extern "C" void kernel_launch(void* const* d_in, const int* in_sizes, int n_in,
                              void* d_out, int out_size)
{
    const float* x = (const float*)d_in[0];   // (1, 256, 65536)
    const float* W = (const float*)d_in[1];   // (16, 256, 256, 2) == (16, 256, 512)
    const float* b = (const float*)d_in[2];   // (16, 256)

    __nv_bfloat16 *ahi, *alo, *bhi, *blo, *whi, *wlo;
    cudaGetSymbolAddress((void**)&ahi, g_ahi);
    cudaGetSymbolAddress((void**)&alo, g_alo);
    cudaGetSymbolAddress((void**)&bhi, g_bhi);
    cudaGetSymbolAddress((void**)&blo, g_blo);
    cudaGetSymbolAddress((void**)&whi, g_whi);
    cudaGetSymbolAddress((void**)&wlo, g_wlo);

    const int nW = 16 * 256 * 512;
    prep_w<<<(nW + 255) / 256, 256>>>(W, whi, wlo, nW);

    int Nin = 65536;
    const void* cur_hi = (const void*)x;
    const __nv_bfloat16* cur_lo = nullptr;
    int fp32_in = 1;

    for (int i = 0; i < 16; i++) {
        int Nout = Nin >> 1;
        __nv_bfloat16* ohi = (i & 1) ? bhi : ahi;
        __nv_bfloat16* olo = (i & 1) ? blo : alo;
        float* of = (i == 15) ? (float*)d_out : nullptr;
        dim3 grid((Nout + 127) / 128, 2);
        layer_hmma<<<grid, 256>>>(cur_hi, cur_lo,
                                  whi + (size_t)i * 256 * 512,
                                  wlo + (size_t)i * 256 * 512,
                                  b + i * 256,
                                  ohi, olo, of, Nin, Nout, fp32_in);
        cur_hi = (const void*)ohi;
        cur_lo = olo;
        fp32_in = 0;
        Nin = Nout;
    }
}

// round 9
// speedup vs baseline: 2.3819x; 1.2491x over previous
#include <cuda_runtime.h>
#include <cuda_bf16.h>
#include <cstdint>
#include <math.h>

// ============================================================
// bf16-split GEMM per layer via mma.sync (HMMA).
//   layer i: out[c,j] = tanh( sum_k W[c,k]*B[k,j] + bias[c] )
//   B[k][j] = in[k>>1][2j + (k&1)]   (compacted dilated conv)
//   fp32 ~= bf16 hi+lo:  A*B ~= Ah*Bh + Ah*Bl + Al*Bh
// Activations carried between layers as bf16 hi/lo planes.
// R9: R5 structure (known good) + register-staged double
//     buffering of global loads (prefetch chunk c+1 into regs
//     during compute of chunk c). No layout changes.
// ============================================================

#define RS 80   // smem row stride in bytes (64B payload + pad)

// ---------------- scratch ----------------
__device__ __nv_bfloat16 g_ahi[256 * 32768];
__device__ __nv_bfloat16 g_alo[256 * 32768];
__device__ __nv_bfloat16 g_bhi[256 * 16384];
__device__ __nv_bfloat16 g_blo[256 * 16384];
__device__ __nv_bfloat16 g_whi[16 * 256 * 512];
__device__ __nv_bfloat16 g_wlo[16 * 256 * 512];

// ---------------- helpers ----------------
__device__ __forceinline__ void ldsm_x4(uint32_t* r, uint32_t addr) {
    asm volatile("ldmatrix.sync.aligned.m8n8.x4.shared.b16 {%0,%1,%2,%3}, [%4];"
        : "=r"(r[0]), "=r"(r[1]), "=r"(r[2]), "=r"(r[3]) : "r"(addr));
}

__device__ __forceinline__ void mma_bf16(float* c, const uint32_t* a, const uint32_t* b) {
    asm volatile(
        "mma.sync.aligned.m16n8k16.row.col.f32.bf16.bf16.f32 "
        "{%0,%1,%2,%3}, {%4,%5,%6,%7}, {%8,%9}, {%0,%1,%2,%3};"
        : "+f"(c[0]), "+f"(c[1]), "+f"(c[2]), "+f"(c[3])
        : "r"(a[0]), "r"(a[1]), "r"(a[2]), "r"(a[3]), "r"(b[0]), "r"(b[1]));
}

// split two floats into packed-bf16 hi pair and lo (residual) pair
__device__ __forceinline__ void split2(float x, float y, uint32_t& h, uint32_t& l) {
    __nv_bfloat16 hx = __float2bfloat16(x);
    __nv_bfloat16 hy = __float2bfloat16(y);
    __nv_bfloat162 hp; hp.x = hx; hp.y = hy;
    __nv_bfloat162 lp;
    lp.x = __float2bfloat16(x - __bfloat162float(hx));
    lp.y = __float2bfloat16(y - __bfloat162float(hy));
    h = *reinterpret_cast<uint32_t*>(&hp);
    l = *reinterpret_cast<uint32_t*>(&lp);
}

// ---------------- weight hi/lo split ----------------
__global__ void prep_w(const float* __restrict__ W,
                       __nv_bfloat16* __restrict__ hi,
                       __nv_bfloat16* __restrict__ lo, int n) {
    int i = blockIdx.x * blockDim.x + threadIdx.x;
    if (i < n) {
        float v = W[i];
        __nv_bfloat16 h = __float2bfloat16(v);
        hi[i] = h;
        lo[i] = __float2bfloat16(v - __bfloat162float(h));
    }
}

// ---------------- per-layer GEMM kernel ----------------
// CTA: 256 threads = 8 warps in 2(M) x 4(N) grid; tile 128x128, BK=32.
__global__ __launch_bounds__(256) void layer_hmma(
    const void* __restrict__ in_hi,          // bf16 plane, or fp32 if fp32_in
    const __nv_bfloat16* __restrict__ in_lo, // bf16 lo plane (ignored if fp32_in)
    const __nv_bfloat16* __restrict__ Whi,   // 256 x 512
    const __nv_bfloat16* __restrict__ Wlo,
    const float* __restrict__ bias,          // 256
    __nv_bfloat16* __restrict__ out_hi,      // 256 x Nout
    __nv_bfloat16* __restrict__ out_lo,
    float* __restrict__ out_f,               // non-null on final layer (Nout==1)
    int Nin, int Nout, int fp32_in)
{
    __shared__ __align__(16) char sAh[128 * RS];
    __shared__ __align__(16) char sAl[128 * RS];
    __shared__ __align__(16) char sBh[128 * RS];
    __shared__ __align__(16) char sBl[128 * RS];

    const int tid  = threadIdx.x;
    const int lane = tid & 31;
    const int wid  = tid >> 5;
    const int wm   = wid & 1;     // 0..1 : 64-row slab
    const int wn   = wid >> 1;    // 0..3 : 32-col slab
    const int m0   = blockIdx.y * 128;
    const int j0   = blockIdx.x * 128;

    float acc[4][4][4];
    #pragma unroll
    for (int a = 0; a < 4; a++)
        #pragma unroll
        for (int b = 0; b < 4; b++)
            #pragma unroll
            for (int c = 0; c < 4; c++) acc[a][b][c] = 0.f;

    const uint32_t sAh_u = (uint32_t)__cvta_generic_to_shared(sAh);
    const uint32_t sAl_u = (uint32_t)__cvta_generic_to_shared(sAl);
    const uint32_t sBh_u = (uint32_t)__cvta_generic_to_shared(sBh);
    const uint32_t sBl_u = (uint32_t)__cvta_generic_to_shared(sBl);

    // ldmatrix per-lane source rows
    const int a_row = lane & 15;
    const int a_cb  = lane >> 4;
    const int b_row = (lane & 7) + ((lane >> 4) << 3);
    const int b_cb  = (lane >> 3) & 1;

    // loader mapping
    const int l_arow = tid >> 1, l_ahalf = tid & 1;   // A: 128 rows x 2 halves
    const int l_c = tid & 15, l_seg = tid >> 4;       // B: 16 chans x 16 segments

    // ---- persistent prefetch registers ----
    uint4 pAh0, pAh1, pAl0, pAl1;
    uint4 pBh0, pBh1, pBl0, pBl1;

    auto load_g = [&](int chunk) {
        const int k0 = chunk * 32;
        // A: 128 x 32 bf16 (hi & lo)
        {
            size_t gofs = (size_t)(m0 + l_arow) * 512 + k0 + l_ahalf * 16;
            const uint4* ph = reinterpret_cast<const uint4*>(Whi + gofs);
            const uint4* pl = reinterpret_cast<const uint4*>(Wlo + gofs);
            pAh0 = ph[0]; pAh1 = ph[1];
            pAl0 = pl[0]; pAl1 = pl[1];
        }
        // B: 16 consecutive times per thread
        {
            const int ch = (k0 >> 1) + l_c;
            const int t  = 2 * j0 + l_seg * 16;
            if (fp32_in) {
                const float* p = reinterpret_cast<const float*>(in_hi) + (size_t)ch * Nin + t;
                uint32_t vh[8], vl[8];
                if (t + 15 < Nin) {
                    #pragma unroll
                    for (int q = 0; q < 4; q++) {
                        float4 f = reinterpret_cast<const float4*>(p)[q];
                        split2(f.x, f.y, vh[2 * q],     vl[2 * q]);
                        split2(f.z, f.w, vh[2 * q + 1], vl[2 * q + 1]);
                    }
                } else {
                    #pragma unroll
                    for (int q = 0; q < 8; q++) {
                        float f0 = (t + 2 * q     < Nin) ? p[2 * q]     : 0.f;
                        float f1 = (t + 2 * q + 1 < Nin) ? p[2 * q + 1] : 0.f;
                        split2(f0, f1, vh[q], vl[q]);
                    }
                }
                pBh0 = make_uint4(vh[0], vh[1], vh[2], vh[3]);
                pBh1 = make_uint4(vh[4], vh[5], vh[6], vh[7]);
                pBl0 = make_uint4(vl[0], vl[1], vl[2], vl[3]);
                pBl1 = make_uint4(vl[4], vl[5], vl[6], vl[7]);
            } else {
                const __nv_bfloat16* ph = reinterpret_cast<const __nv_bfloat16*>(in_hi) + (size_t)ch * Nin + t;
                const __nv_bfloat16* pl = in_lo + (size_t)ch * Nin + t;
                if (t + 15 < Nin) {
                    pBh0 = reinterpret_cast<const uint4*>(ph)[0];
                    pBh1 = reinterpret_cast<const uint4*>(ph)[1];
                    pBl0 = reinterpret_cast<const uint4*>(pl)[0];
                    pBl1 = reinterpret_cast<const uint4*>(pl)[1];
                } else {
                    uint32_t vh[8], vl[8];
                    #pragma unroll
                    for (int q = 0; q < 8; q++) {
                        __nv_bfloat162 hp, lp;
                        hp.x = (t + 2 * q     < Nin) ? ph[2 * q]     : __nv_bfloat16(0.f);
                        hp.y = (t + 2 * q + 1 < Nin) ? ph[2 * q + 1] : __nv_bfloat16(0.f);
                        lp.x = (t + 2 * q     < Nin) ? pl[2 * q]     : __nv_bfloat16(0.f);
                        lp.y = (t + 2 * q + 1 < Nin) ? pl[2 * q + 1] : __nv_bfloat16(0.f);
                        vh[q] = *reinterpret_cast<uint32_t*>(&hp);
                        vl[q] = *reinterpret_cast<uint32_t*>(&lp);
                    }
                    pBh0 = make_uint4(vh[0], vh[1], vh[2], vh[3]);
                    pBh1 = make_uint4(vh[4], vh[5], vh[6], vh[7]);
                    pBl0 = make_uint4(vl[0], vl[1], vl[2], vl[3]);
                    pBl1 = make_uint4(vl[4], vl[5], vl[6], vl[7]);
                }
            }
        }
    };

    auto store_smem = [&]() {
        char* dh = sAh + l_arow * RS + l_ahalf * 32;
        char* dl = sAl + l_arow * RS + l_ahalf * 32;
        reinterpret_cast<uint4*>(dh)[0] = pAh0;
        reinterpret_cast<uint4*>(dh)[1] = pAh1;
        reinterpret_cast<uint4*>(dl)[0] = pAl0;
        reinterpret_cast<uint4*>(dl)[1] = pAl1;
        char* dbh = sBh + (l_seg * 8) * RS + 4 * l_c;
        char* dbl = sBl + (l_seg * 8) * RS + 4 * l_c;
        uint32_t vh[8] = {pBh0.x, pBh0.y, pBh0.z, pBh0.w, pBh1.x, pBh1.y, pBh1.z, pBh1.w};
        uint32_t vl[8] = {pBl0.x, pBl0.y, pBl0.z, pBl0.w, pBl1.x, pBl1.y, pBl1.z, pBl1.w};
        #pragma unroll
        for (int q = 0; q < 8; q++) {
            *reinterpret_cast<uint32_t*>(dbh + q * RS) = vh[q];
            *reinterpret_cast<uint32_t*>(dbl + q * RS) = vl[q];
        }
    };

    load_g(0);
    for (int chunk = 0; chunk < 16; chunk++) {
        store_smem();
        __syncthreads();
        if (chunk + 1 < 16) load_g(chunk + 1);   // LDGs in flight during compute

        // ---- compute: 2 k16 steps x (AhBh + AhBl + AlBh) ----
        #pragma unroll
        for (int ks = 0; ks < 2; ks++) {
            uint32_t af[4][4], bh[4][2], bl[4][2];
            #pragma unroll
            for (int mt = 0; mt < 4; mt++) {
                uint32_t ofs = (uint32_t)((wm * 64 + mt * 16 + a_row) * RS + ks * 32 + a_cb * 16);
                ldsm_x4(af[mt], sAh_u + ofs);
            }
            #pragma unroll
            for (int half = 0; half < 2; half++) {
                uint32_t ofs = (uint32_t)((wn * 32 + half * 16 + b_row) * RS + ks * 32 + b_cb * 16);
                uint32_t r[4];
                ldsm_x4(r, sBh_u + ofs);
                bh[half * 2][0] = r[0]; bh[half * 2][1] = r[1];
                bh[half * 2 + 1][0] = r[2]; bh[half * 2 + 1][1] = r[3];
                ldsm_x4(r, sBl_u + ofs);
                bl[half * 2][0] = r[0]; bl[half * 2][1] = r[1];
                bl[half * 2 + 1][0] = r[2]; bl[half * 2 + 1][1] = r[3];
            }
            #pragma unroll
            for (int mt = 0; mt < 4; mt++)
                #pragma unroll
                for (int nt = 0; nt < 4; nt++) {
                    mma_bf16(acc[mt][nt], af[mt], bh[nt]);
                    mma_bf16(acc[mt][nt], af[mt], bl[nt]);
                }
            #pragma unroll
            for (int mt = 0; mt < 4; mt++) {
                uint32_t ofs = (uint32_t)((wm * 64 + mt * 16 + a_row) * RS + ks * 32 + a_cb * 16);
                ldsm_x4(af[mt], sAl_u + ofs);
            }
            #pragma unroll
            for (int mt = 0; mt < 4; mt++)
                #pragma unroll
                for (int nt = 0; nt < 4; nt++)
                    mma_bf16(acc[mt][nt], af[mt], bh[nt]);
        }
        __syncthreads();
    }

    // ---- epilogue: bias + tanh; write bf16 hi/lo planes (or fp32 final) ----
    const int g = lane >> 2, tig = lane & 3;
    #pragma unroll
    for (int mt = 0; mt < 4; mt++) {
        const int mA = m0 + wm * 64 + mt * 16 + g;
        const int mB = mA + 8;
        const float bA = bias[mA], bB = bias[mB];
        #pragma unroll
        for (int nt = 0; nt < 4; nt++) {
            const int col = j0 + wn * 32 + nt * 8 + 2 * tig;
            float v0 = tanhf(acc[mt][nt][0] + bA);
            float v1 = tanhf(acc[mt][nt][1] + bA);
            float v2 = tanhf(acc[mt][nt][2] + bB);
            float v3 = tanhf(acc[mt][nt][3] + bB);
            if (out_f) {
                if (col == 0) { out_f[mA] = v0; out_f[mB] = v2; }
            } else if (col < Nout) {   // Nout even for all intermediate layers
                uint32_t h, l;
                split2(v0, v1, h, l);
                *reinterpret_cast<uint32_t*>(out_hi + (size_t)mA * Nout + col) = h;
                *reinterpret_cast<uint32_t*>(out_lo + (size_t)mA * Nout + col) = l;
                split2(v2, v3, h, l);
                *reinterpret_cast<uint32_t*>(out_hi + (size_t)mB * Nout + col) = h;
                *reinterpret_cast<uint32_t*>(out_lo + (size_t)mB * Nout + col) = l;
            }
        }
    }
}

// ---------------- host ----------------
extern "C" void kernel_launch(void* const* d_in, const int* in_sizes, int n_in,
                              void* d_out, int out_size)
{
    const float* x = (const float*)d_in[0];   // (1, 256, 65536)
    const float* W = (const float*)d_in[1];   // (16, 256, 256, 2) == (16, 256, 512)
    const float* b = (const float*)d_in[2];   // (16, 256)

    __nv_bfloat16 *ahi, *alo, *bhi, *blo, *whi, *wlo;
    cudaGetSymbolAddress((void**)&ahi, g_ahi);
    cudaGetSymbolAddress((void**)&alo, g_alo);
    cudaGetSymbolAddress((void**)&bhi, g_bhi);
    cudaGetSymbolAddress((void**)&blo, g_blo);
    cudaGetSymbolAddress((void**)&whi, g_whi);
    cudaGetSymbolAddress((void**)&wlo, g_wlo);

    const int nW = 16 * 256 * 512;
    prep_w<<<(nW + 255) / 256, 256>>>(W, whi, wlo, nW);

    int Nin = 65536;
    const void* cur_hi = (const void*)x;
    const __nv_bfloat16* cur_lo = nullptr;
    int fp32_in = 1;

    for (int i = 0; i < 16; i++) {
        int Nout = Nin >> 1;
        __nv_bfloat16* ohi = (i & 1) ? bhi : ahi;
        __nv_bfloat16* olo = (i & 1) ? blo : alo;
        float* of = (i == 15) ? (float*)d_out : nullptr;
        dim3 grid((Nout + 127) / 128, 2);
        layer_hmma<<<grid, 256>>>(cur_hi, cur_lo,
                                  whi + (size_t)i * 256 * 512,
                                  wlo + (size_t)i * 256 * 512,
                                  b + i * 256,
                                  ohi, olo, of, Nin, Nout, fp32_in);
        cur_hi = (const void*)ohi;
        cur_lo = olo;
        fp32_in = 0;
        Nin = Nout;
    }
}